// round 2
// baseline (speedup 1.0000x reference)
#include <cuda_runtime.h>
#include <math.h>

#define BATCH 4
#define SEQ   4096
#define CH    1024
#define HS    64

// Scratch for projected q, k, v: [B*T, HS] each (4 MB each).
__device__ float g_q[BATCH * SEQ * HS];
__device__ float g_k[BATCH * SEQ * HS];
__device__ float g_v[BATCH * SEQ * HS];

// ---------------------------------------------------------------------------
// Kernel 1: QKV projection.  out[m, n] = sum_k x[m, k] * W[k, n]
// M = B*T = 16384, N = 64, K = 1024.  grid = (M/64, 3), block = 256.
// ---------------------------------------------------------------------------
__global__ __launch_bounds__(256) void qkv_kernel(
    const float* __restrict__ x,
    const float* __restrict__ Wq,
    const float* __restrict__ Wk,
    const float* __restrict__ Wv)
{
    __shared__ __align__(16) float xs[64][33];   // x tile, padded
    __shared__ __align__(16) float ws[32][64];   // W tile

    const float* W  = (blockIdx.y == 0) ? Wq : (blockIdx.y == 1) ? Wk : Wv;
    float*       dst = (blockIdx.y == 0) ? g_q : (blockIdx.y == 1) ? g_k : g_v;

    const int row0 = blockIdx.x * 64;
    const int tid  = threadIdx.x;
    const int tx   = tid & 15;
    const int ty   = tid >> 4;

    float acc[4][4] = {};

    for (int k0 = 0; k0 < CH; k0 += 32) {
        // load x tile: 64 rows x 32 cols = 512 float4
        for (int i = tid; i < 512; i += 256) {
            int r = i >> 3, c4 = i & 7;
            float4 v = *(const float4*)(x + (size_t)(row0 + r) * CH + k0 + c4 * 4);
            xs[r][c4 * 4 + 0] = v.x;
            xs[r][c4 * 4 + 1] = v.y;
            xs[r][c4 * 4 + 2] = v.z;
            xs[r][c4 * 4 + 3] = v.w;
        }
        // load W tile: 32 rows x 64 cols = 512 float4
        for (int i = tid; i < 512; i += 256) {
            int r = i >> 4, c4 = i & 15;
            *(float4*)&ws[r][c4 * 4] =
                *(const float4*)(W + (size_t)(k0 + r) * HS + c4 * 4);
        }
        __syncthreads();

        #pragma unroll
        for (int kk = 0; kk < 32; kk++) {
            float a[4];
            #pragma unroll
            for (int i = 0; i < 4; i++) a[i] = xs[ty * 4 + i][kk];
            float4 bv = *(float4*)&ws[kk][tx * 4];
            #pragma unroll
            for (int i = 0; i < 4; i++) {
                acc[i][0] += a[i] * bv.x;
                acc[i][1] += a[i] * bv.y;
                acc[i][2] += a[i] * bv.z;
                acc[i][3] += a[i] * bv.w;
            }
        }
        __syncthreads();
    }

    #pragma unroll
    for (int i = 0; i < 4; i++) {
        float4 o = make_float4(acc[i][0], acc[i][1], acc[i][2], acc[i][3]);
        *(float4*)(dst + (size_t)(row0 + ty * 4 + i) * HS + tx * 4) = o;
    }
}

// ---------------------------------------------------------------------------
// Kernel 2: causal flash attention, fp32.
// Each block handles TWO query tiles: qb = 63-bx (heavy) then qb = bx,
// so every block processes exactly 65 key tiles -> balanced single wave.
// grid = (32, BATCH), block = 256, dynamic smem = 4 * 64 * 68 * 4 bytes.
// ---------------------------------------------------------------------------
#define PAD 68
#define SMEM_BYTES (4 * 64 * PAD * 4)

__global__ __launch_bounds__(256, 2) void attn_kernel(float* __restrict__ out)
{
    extern __shared__ __align__(16) float smem[];
    float* Qs = smem;
    float* Ks = Qs + 64 * PAD;
    float* Vs = Ks + 64 * PAD;
    float* Ps = Vs + 64 * PAD;

    const int b   = blockIdx.y;
    const int bx  = blockIdx.x;          // 0..31
    const int tid = threadIdx.x;
    const int tx  = tid & 15;
    const int ty  = tid >> 4;

    const float* kg = g_k + (size_t)b * SEQ * HS;
    const float* vg = g_v + (size_t)b * SEQ * HS;

    for (int pass = 0; pass < 2; pass++) {
        const int qb = (pass == 0) ? (63 - bx) : bx;
        const float* qg = g_q + ((size_t)b * SEQ + qb * 64) * HS;

        // load Q tile (64x64) into smem
        for (int i = tid; i < 1024; i += 256) {
            int r = i >> 4, c4 = i & 15;
            *(float4*)&Qs[r * PAD + c4 * 4] =
                *(const float4*)(qg + r * HS + c4 * 4);
        }

        float O[4][4] = {};
        float m[4], l[4];
        #pragma unroll
        for (int i = 0; i < 4; i++) { m[i] = -1e30f; l[i] = 0.f; }

        for (int j0 = 0; j0 <= qb; j0++) {
            // load K, V tiles (64x64 each)
            for (int i = tid; i < 1024; i += 256) {
                int r = i >> 4, c4 = i & 15;
                *(float4*)&Ks[r * PAD + c4 * 4] =
                    *(const float4*)(kg + (size_t)(j0 * 64 + r) * HS + c4 * 4);
                *(float4*)&Vs[r * PAD + c4 * 4] =
                    *(const float4*)(vg + (size_t)(j0 * 64 + r) * HS + c4 * 4);
            }
            __syncthreads();

            // S = Q @ K^T  (thread computes 4x4 tile)
            float S[4][4] = {};
            #pragma unroll 4
            for (int h = 0; h < 64; h += 4) {
                float4 qv[4], kv[4];
                #pragma unroll
                for (int i = 0; i < 4; i++)
                    qv[i] = *(float4*)&Qs[(ty * 4 + i) * PAD + h];
                #pragma unroll
                for (int j = 0; j < 4; j++)
                    kv[j] = *(float4*)&Ks[(tx * 4 + j) * PAD + h];
                #pragma unroll
                for (int i = 0; i < 4; i++)
                    #pragma unroll
                    for (int j = 0; j < 4; j++)
                        S[i][j] += qv[i].x * kv[j].x + qv[i].y * kv[j].y +
                                   qv[i].z * kv[j].z + qv[i].w * kv[j].w;
            }

            const bool diag = (j0 == qb);

            // online softmax per row
            #pragma unroll
            for (int i = 0; i < 4; i++) {
                const int lrow = ty * 4 + i;
                float mloc = -1e30f;
                #pragma unroll
                for (int j = 0; j < 4; j++) {
                    float sv = S[i][j] * 0.125f;          // HS^-0.5
                    if (diag && (tx * 4 + j) > lrow) sv = -1e30f;
                    S[i][j] = sv;
                    mloc = fmaxf(mloc, sv);
                }
                #pragma unroll
                for (int off = 8; off >= 1; off >>= 1)
                    mloc = fmaxf(mloc, __shfl_xor_sync(0xffffffffu, mloc, off));

                float mnew  = fmaxf(m[i], mloc);
                float alpha = __expf(m[i] - mnew);
                float rsum  = 0.f;
                #pragma unroll
                for (int j = 0; j < 4; j++) {
                    float p = __expf(S[i][j] - mnew);
                    S[i][j] = p;
                    rsum += p;
                }
                #pragma unroll
                for (int off = 8; off >= 1; off >>= 1)
                    rsum += __shfl_xor_sync(0xffffffffu, rsum, off);

                l[i] = l[i] * alpha + rsum;
                m[i] = mnew;
                #pragma unroll
                for (int j = 0; j < 4; j++) O[i][j] *= alpha;
            }

            // write P to smem for the PV gemm
            #pragma unroll
            for (int i = 0; i < 4; i++)
                *(float4*)&Ps[(ty * 4 + i) * PAD + tx * 4] =
                    make_float4(S[i][0], S[i][1], S[i][2], S[i][3]);
            __syncthreads();

            // O += P @ V
            #pragma unroll 4
            for (int kk = 0; kk < 64; kk += 4) {
                float4 pv[4], vv[4];
                #pragma unroll
                for (int i = 0; i < 4; i++)
                    pv[i] = *(float4*)&Ps[(ty * 4 + i) * PAD + kk];
                #pragma unroll
                for (int c = 0; c < 4; c++)
                    vv[c] = *(float4*)&Vs[(kk + c) * PAD + tx * 4];
                #pragma unroll
                for (int i = 0; i < 4; i++) {
                    O[i][0] += pv[i].x * vv[0].x + pv[i].y * vv[1].x +
                               pv[i].z * vv[2].x + pv[i].w * vv[3].x;
                    O[i][1] += pv[i].x * vv[0].y + pv[i].y * vv[1].y +
                               pv[i].z * vv[2].y + pv[i].w * vv[3].y;
                    O[i][2] += pv[i].x * vv[0].z + pv[i].y * vv[1].z +
                               pv[i].z * vv[2].z + pv[i].w * vv[3].z;
                    O[i][3] += pv[i].x * vv[0].w + pv[i].y * vv[1].w +
                               pv[i].z * vv[2].w + pv[i].w * vv[3].w;
                }
            }
            __syncthreads();
        }

        // epilogue: normalize and write out
        #pragma unroll
        for (int i = 0; i < 4; i++) {
            float inv = 1.0f / l[i];
            float4 o = make_float4(O[i][0] * inv, O[i][1] * inv,
                                   O[i][2] * inv, O[i][3] * inv);
            *(float4*)(out + ((size_t)b * SEQ + qb * 64 + ty * 4 + i) * HS +
                       tx * 4) = o;
        }
        // smem reuse across passes is protected by the loop-end __syncthreads()
    }
}

// ---------------------------------------------------------------------------
extern "C" void kernel_launch(void* const* d_in, const int* in_sizes, int n_in,
                              void* d_out, int out_size)
{
    const float* x  = (const float*)d_in[0];
    const float* Wq = (const float*)d_in[1];
    const float* Wk = (const float*)d_in[2];
    const float* Wv = (const float*)d_in[3];
    float* out = (float*)d_out;

    cudaFuncSetAttribute(attn_kernel,
                         cudaFuncAttributeMaxDynamicSharedMemorySize,
                         SMEM_BYTES);

    // QKV projection: grid (M/64, 3)
    qkv_kernel<<<dim3(BATCH * SEQ / 64, 3), 256>>>(x, Wq, Wk, Wv);

    // Flash attention: 32 paired query-tile blocks per batch (balanced wave)
    attn_kernel<<<dim3(32, BATCH), 256, SMEM_BYTES>>>(out);
}

// round 4
// speedup vs baseline: 1.8223x; 1.8223x over previous
#include <cuda_runtime.h>
#include <cstdint>

#define BATCH 4
#define SEQ   4096
#define CH    1024
#define HS    64

__device__ float g_q[BATCH*SEQ*HS];
__device__ float g_k[BATCH*SEQ*HS];
__device__ float g_v[BATCH*SEQ*HS];

// ---------------------------------------------------------------- primitives
__device__ __forceinline__ uint32_t f2tf(float f){
    uint32_t u; asm("cvt.rna.tf32.f32 %0, %1;" : "=r"(u) : "f"(f)); return u;
}
__device__ __forceinline__ float ex2f(float x){
    float y; asm("ex2.approx.ftz.f32 %0, %1;" : "=f"(y) : "f"(x)); return y;
}
// D(16x8) += A(16x8, tf32) * B(8x8, tf32)
__device__ __forceinline__ void mma8(float* d, const uint32_t* a, const uint32_t* b){
    asm volatile("mma.sync.aligned.m16n8k8.row.col.f32.tf32.tf32.f32 "
        "{%0,%1,%2,%3}, {%4,%5,%6,%7}, {%8,%9}, {%0,%1,%2,%3};"
        : "+f"(d[0]), "+f"(d[1]), "+f"(d[2]), "+f"(d[3])
        : "r"(a[0]), "r"(a[1]), "r"(a[2]), "r"(a[3]), "r"(b[0]), "r"(b[1]));
}
// k-interleave permutation: maps k, k+4 (within an 8-block) to adjacent slots
__device__ __forceinline__ int hp(int h){
    return (h & ~7) + ((h & 3) << 1) + ((h >> 2) & 1);
}

#define C_EXP 0.18033688011112042f   // (1/8) * log2(e)

// ---------------------------------------------------------------- QKV kernel
// grid 128, block 256 (8 warps, M=16 rows/warp), fused N = 192 (q|k|v).
#define QKV_SMEM ((128*68 + 192*68) * 4)
__global__ __launch_bounds__(256, 1) void qkv_tc(
    const float* __restrict__ x,  const float* __restrict__ Wq,
    const float* __restrict__ Wk, const float* __restrict__ Wv)
{
    extern __shared__ __align__(16) uint32_t sm[];
    uint32_t* xs = sm;             // [128 rows][68]  cols = hp(k)
    uint32_t* wt = sm + 128*68;    // [192 n  ][68]  cols = hp(k)
    const int tid = threadIdx.x, w = tid >> 5, ln = tid & 31;
    const int m = ln & 3, qr = ln >> 2;
    const int row0 = blockIdx.x * 128;
    const float* Ws[3] = {Wq, Wk, Wv};

    float o[24][4];
    #pragma unroll
    for (int i = 0; i < 24; i++) { o[i][0]=o[i][1]=o[i][2]=o[i][3]=0.f; }

    const int wr = tid & 63;        // W fill: this thread's k-row
    const int wg = tid >> 6;        // and hs quarter

    #pragma unroll 1
    for (int c = 0; c < 16; c++) {
        const int k0 = c * 64;
        // x tile fill: [128][64], cols permuted
        #pragma unroll
        for (int i = 0; i < 8; i++) {
            int idx = tid + i*256, r = idx >> 4, c4 = idx & 15;
            float4 v = *(const float4*)(x + (size_t)(row0+r)*CH + k0 + c4*4);
            xs[r*68 + hp(c4*4+0)] = f2tf(v.x);
            xs[r*68 + hp(c4*4+1)] = f2tf(v.y);
            xs[r*68 + hp(c4*4+2)] = f2tf(v.z);
            xs[r*68 + hp(c4*4+3)] = f2tf(v.w);
        }
        // W tiles fill (transposed): wt[n][hp(k)], per-thread-k-row mapping
        #pragma unroll
        for (int ww = 0; ww < 3; ww++) {
            #pragma unroll
            for (int j = 0; j < 4; j++) {
                int hs0 = wg*16 + j*4;
                float4 v = *(const float4*)(Ws[ww] + (size_t)(k0+wr)*HS + hs0);
                int col = hp(wr);
                wt[(ww*64 + hs0+0)*68 + col] = f2tf(v.x);
                wt[(ww*64 + hs0+1)*68 + col] = f2tf(v.y);
                wt[(ww*64 + hs0+2)*68 + col] = f2tf(v.z);
                wt[(ww*64 + hs0+3)*68 + col] = f2tf(v.w);
            }
        }
        __syncthreads();

        const int arow = w*16 + qr;
        #pragma unroll 1
        for (int ks = 0; ks < 8; ks++) {
            uint32_t a[4];
            uint2 t0 = *(uint2*)&xs[arow*68 + ks*8 + 2*m];
            uint2 t1 = *(uint2*)&xs[(arow+8)*68 + ks*8 + 2*m];
            a[0]=t0.x; a[2]=t0.y; a[1]=t1.x; a[3]=t1.y;
            #pragma unroll
            for (int nt = 0; nt < 24; nt++) {
                uint2 bb = *(uint2*)&wt[(nt*8+qr)*68 + ks*8 + 2*m];
                uint32_t b[2] = {bb.x, bb.y};
                mma8(o[nt], a, b);
            }
        }
        __syncthreads();
    }
    // epilogue
    float* dsts[3] = {g_q, g_k, g_v};
    const int rg = row0 + w*16 + qr;
    #pragma unroll
    for (int nt = 0; nt < 24; nt++) {
        float* d = dsts[nt >> 3];
        int col = (nt & 7)*8 + 2*m;
        *(float2*)(d + (size_t)rg*HS + col)     = make_float2(o[nt][0], o[nt][1]);
        *(float2*)(d + (size_t)(rg+8)*HS + col) = make_float2(o[nt][2], o[nt][3]);
    }
}

// ----------------------------------------------------------- attention kernel
// grid 128 (4 b x 32 qtiles of 128), block 128 (4 warps, M=32 rows/warp).
// Q fragments register-resident; no max subtraction; O never rescaled.
#define ATT_SMEM ((128*68 + 64*132 + 4*32*132) * 4)
__global__ __launch_bounds__(128, 1) void attn_tc(float* __restrict__ out)
{
    extern __shared__ __align__(16) uint32_t sm[];
    uint32_t* Ksm = sm;                       // [128 key][68]   cols = hp(hs)
    uint32_t* VT  = sm + 128*68;              // [64  hs ][132]  cols = hp(key)
    uint32_t* Ps  = VT + 64*132 + (threadIdx.x >> 5)*32*132;  // [32 row][132] cols = hp(key)
    const int tid = threadIdx.x, w = tid >> 5, ln = tid & 31;
    const int m = ln & 3, qr = ln >> 2;
    const int b = blockIdx.x >> 5, qt = blockIdx.x & 31;
    const float* qg = g_q + ((size_t)b*SEQ + qt*128) * HS;
    const float* kg = g_k + (size_t)b*SEQ*HS;
    const float* vg = g_v + (size_t)b*SEQ*HS;

    // stage Q tile in Ksm area, then pull fragments to registers
    #pragma unroll
    for (int i = 0; i < 16; i++) {
        int idx = tid + i*128, r = idx >> 4, c4 = idx & 15;
        float4 v = *(const float4*)(qg + (size_t)r*HS + c4*4);
        Ksm[r*68 + hp(c4*4+0)] = f2tf(v.x);
        Ksm[r*68 + hp(c4*4+1)] = f2tf(v.y);
        Ksm[r*68 + hp(c4*4+2)] = f2tf(v.z);
        Ksm[r*68 + hp(c4*4+3)] = f2tf(v.w);
    }
    __syncthreads();
    uint32_t q[2][8][4];
    #pragma unroll
    for (int mt = 0; mt < 2; mt++) {
        int r = w*32 + mt*16 + qr;
        #pragma unroll
        for (int ks = 0; ks < 8; ks++) {
            uint2 t0 = *(uint2*)&Ksm[r*68 + ks*8 + 2*m];
            uint2 t1 = *(uint2*)&Ksm[(r+8)*68 + ks*8 + 2*m];
            q[mt][ks][0]=t0.x; q[mt][ks][2]=t0.y; q[mt][ks][1]=t1.x; q[mt][ks][3]=t1.y;
        }
    }
    __syncthreads();

    float o[2][8][4];
    #pragma unroll
    for (int mt = 0; mt < 2; mt++)
        #pragma unroll
        for (int nt = 0; nt < 8; nt++)
            { o[mt][nt][0]=o[mt][nt][1]=o[mt][nt][2]=o[mt][nt][3]=0.f; }
    float l[4] = {0.f, 0.f, 0.f, 0.f};     // [mt*2 + rowhalf]

    const int pe0 = (((2*m) & 3) << 1) | ((2*m) >> 2);
    const int pe1 = (((2*m+1) & 3) << 1) | ((2*m+1) >> 2);

    #pragma unroll 1
    for (int jt = 0; jt <= qt; jt++) {
        const float* kt = kg + (size_t)jt*128*HS;
        const float* vt = vg + (size_t)jt*128*HS;
        // K fill: [key][hp(hs)]
        #pragma unroll
        for (int i = 0; i < 16; i++) {
            int idx = tid + i*128, r = idx >> 4, c4 = idx & 15;
            float4 v = *(const float4*)(kt + (size_t)r*HS + c4*4);
            Ksm[r*68 + hp(c4*4+0)] = f2tf(v.x);
            Ksm[r*68 + hp(c4*4+1)] = f2tf(v.y);
            Ksm[r*68 + hp(c4*4+2)] = f2tf(v.z);
            Ksm[r*68 + hp(c4*4+3)] = f2tf(v.w);
        }
        // V fill transposed: VT[hs][hp(key)], per-thread-key mapping (bank-clean)
        {
            int col = hp(tid);   // tid == key row, block == 128
            #pragma unroll
            for (int j = 0; j < 16; j++) {
                float4 v = *(const float4*)(vt + (size_t)tid*HS + j*4);
                VT[(j*4+0)*132 + col] = f2tf(v.x);
                VT[(j*4+1)*132 + col] = f2tf(v.y);
                VT[(j*4+2)*132 + col] = f2tf(v.z);
                VT[(j*4+3)*132 + col] = f2tf(v.w);
            }
        }
        __syncthreads();

        const bool diag = (jt == qt);
        // S = Q K^T in 4 chunks of 32 keys; softmax; P -> Ps
        #pragma unroll 1
        for (int ch = 0; ch < 4; ch++) {
            float s[2][4][4];
            #pragma unroll
            for (int mt = 0; mt < 2; mt++)
                #pragma unroll
                for (int nt = 0; nt < 4; nt++)
                    { s[mt][nt][0]=s[mt][nt][1]=s[mt][nt][2]=s[mt][nt][3]=0.f; }
            #pragma unroll 1
            for (int ks = 0; ks < 8; ks++) {
                #pragma unroll
                for (int nt = 0; nt < 4; nt++) {
                    uint2 bb = *(uint2*)&Ksm[(ch*32+nt*8+qr)*68 + ks*8 + 2*m];
                    uint32_t bfr[2] = {bb.x, bb.y};
                    mma8(s[0][nt], q[0][ks], bfr);
                    mma8(s[1][nt], q[1][ks], bfr);
                }
            }
            #pragma unroll
            for (int mt = 0; mt < 2; mt++) {
                const int lr  = mt*16 + qr;
                const int rg0 = qt*128 + w*32 + lr;
                const int rg1 = rg0 + 8;
                #pragma unroll
                for (int nt = 0; nt < 4; nt++) {
                    const int kb  = ch*32 + nt*8;
                    const int kg0 = jt*128 + kb + 2*m;
                    float p0 = ex2f(s[mt][nt][0] * C_EXP);
                    float p1 = ex2f(s[mt][nt][1] * C_EXP);
                    float p2 = ex2f(s[mt][nt][2] * C_EXP);
                    float p3 = ex2f(s[mt][nt][3] * C_EXP);
                    if (diag) {
                        if (kg0     > rg0) p0 = 0.f;
                        if (kg0 + 1 > rg0) p1 = 0.f;
                        if (kg0     > rg1) p2 = 0.f;
                        if (kg0 + 1 > rg1) p3 = 0.f;
                    }
                    uint32_t u0 = f2tf(p0), u1 = f2tf(p1), u2 = f2tf(p2), u3 = f2tf(p3);
                    l[mt*2+0] += __uint_as_float(u0) + __uint_as_float(u1);
                    l[mt*2+1] += __uint_as_float(u2) + __uint_as_float(u3);
                    Ps[lr*132     + kb + pe0] = u0;
                    Ps[lr*132     + kb + pe1] = u1;
                    Ps[(lr+8)*132 + kb + pe0] = u2;
                    Ps[(lr+8)*132 + kb + pe1] = u3;
                }
            }
        }
        __syncwarp();
        // O += P V
        #pragma unroll 1
        for (int ks = 0; ks < 16; ks++) {
            uint32_t a0[4], a1[4];
            {
                uint2 t0 = *(uint2*)&Ps[qr*132 + ks*8 + 2*m];
                uint2 t1 = *(uint2*)&Ps[(qr+8)*132 + ks*8 + 2*m];
                a0[0]=t0.x; a0[2]=t0.y; a0[1]=t1.x; a0[3]=t1.y;
            }
            {
                uint2 t0 = *(uint2*)&Ps[(16+qr)*132 + ks*8 + 2*m];
                uint2 t1 = *(uint2*)&Ps[(24+qr)*132 + ks*8 + 2*m];
                a1[0]=t0.x; a1[2]=t0.y; a1[1]=t1.x; a1[3]=t1.y;
            }
            #pragma unroll
            for (int nt = 0; nt < 8; nt++) {
                uint2 bb = *(uint2*)&VT[(nt*8+qr)*132 + ks*8 + 2*m];
                uint32_t bfr[2] = {bb.x, bb.y};
                mma8(o[0][nt], a0, bfr);
                mma8(o[1][nt], a1, bfr);
            }
        }
        __syncthreads();
    }

    // reduce l across the quad (lanes sharing a row)
    #pragma unroll
    for (int i = 0; i < 4; i++) {
        l[i] += __shfl_xor_sync(0xffffffffu, l[i], 1);
        l[i] += __shfl_xor_sync(0xffffffffu, l[i], 2);
    }
    // write O / l
    #pragma unroll
    for (int mt = 0; mt < 2; mt++) {
        float inv0 = 1.f / l[mt*2+0];
        float inv1 = 1.f / l[mt*2+1];
        int rg = qt*128 + w*32 + mt*16 + qr;
        float* d = out + ((size_t)b*SEQ + rg) * HS;
        #pragma unroll
        for (int nt = 0; nt < 8; nt++) {
            *(float2*)(d + nt*8 + 2*m) =
                make_float2(o[mt][nt][0]*inv0, o[mt][nt][1]*inv0);
            *(float2*)(d + (size_t)8*HS + nt*8 + 2*m) =
                make_float2(o[mt][nt][2]*inv1, o[mt][nt][3]*inv1);
        }
    }
}

// ---------------------------------------------------------------------------
extern "C" void kernel_launch(void* const* d_in, const int* in_sizes, int n_in,
                              void* d_out, int out_size)
{
    const float* x  = (const float*)d_in[0];
    const float* Wq = (const float*)d_in[1];
    const float* Wk = (const float*)d_in[2];
    const float* Wv = (const float*)d_in[3];
    float* out = (float*)d_out;

    cudaFuncSetAttribute(qkv_tc,  cudaFuncAttributeMaxDynamicSharedMemorySize, QKV_SMEM);
    cudaFuncSetAttribute(attn_tc, cudaFuncAttributeMaxDynamicSharedMemorySize, ATT_SMEM);

    qkv_tc<<<128, 256, QKV_SMEM>>>(x, Wq, Wk, Wv);
    attn_tc<<<128, 128, ATT_SMEM>>>(out);
}

// round 5
// speedup vs baseline: 2.1256x; 1.1665x over previous
#include <cuda_runtime.h>
#include <cstdint>

#define BATCH 4
#define SEQ   4096
#define CH    1024
#define HS    64

__device__ float g_q[BATCH*SEQ*HS];
__device__ float g_k[BATCH*SEQ*HS];
__device__ float g_v[BATCH*SEQ*HS];

// ---------------------------------------------------------------- primitives
__device__ __forceinline__ uint32_t f2tf(float f){
    uint32_t u; asm("cvt.rna.tf32.f32 %0, %1;" : "=r"(u) : "f"(f)); return u;
}
__device__ __forceinline__ float ex2f(float x){
    float y; asm("ex2.approx.ftz.f32 %0, %1;" : "=f"(y) : "f"(x)); return y;
}
__device__ __forceinline__ void mma8(float* d, const uint32_t* a, const uint32_t* b){
    asm volatile("mma.sync.aligned.m16n8k8.row.col.f32.tf32.tf32.f32 "
        "{%0,%1,%2,%3}, {%4,%5,%6,%7}, {%8,%9}, {%0,%1,%2,%3};"
        : "+f"(d[0]), "+f"(d[1]), "+f"(d[2]), "+f"(d[3])
        : "r"(a[0]), "r"(a[1]), "r"(a[2]), "r"(a[3]), "r"(b[0]), "r"(b[1]));
}
// k-interleave permutation: k and k+4 (within an 8-block) become adjacent
__device__ __forceinline__ int hp(int h){
    return (h & ~7) + ((h & 3) << 1) + ((h >> 2) & 1);
}
#define BARG(id) asm volatile("bar.sync %0, 256;" :: "r"(id) : "memory")
#define C_EXP 0.18033688011112042f   // (1/8) * log2(e)

// ---------------------------------------------------------------- QKV kernel
// grid 128, block 512 (16 warps). rows 128/CTA, warps split N=192 two ways.
#define QKV_SMEM ((128*68 + 192*68) * 4)
__global__ __launch_bounds__(512, 1) void qkv_tc(
    const float* __restrict__ x,  const float* __restrict__ Wq,
    const float* __restrict__ Wk, const float* __restrict__ Wv)
{
    extern __shared__ __align__(16) uint32_t sm[];
    uint32_t* xs = sm;             // [128 rows][68]  cols = hp(k)
    uint32_t* wt = sm + 128*68;    // [192 n  ][68]  cols = hp(k)
    const int tid = threadIdx.x, w = tid >> 5, ln = tid & 31;
    const int m = ln & 3, qr = ln >> 2;
    const int wh = w >> 3;          // n-half (0..1)
    const int wrow = (w & 7) * 16;  // warp's row base
    const int row0 = blockIdx.x * 128;
    const float* Ws[3] = {Wq, Wk, Wv};

    float o[12][4];
    #pragma unroll
    for (int i = 0; i < 12; i++) { o[i][0]=o[i][1]=o[i][2]=o[i][3]=0.f; }

    const int wr = tid & 63;        // W fill: k-row
    const int wg = tid >> 6;        // hs octant (0..7)

    #pragma unroll 1
    for (int c = 0; c < 16; c++) {
        const int k0 = c * 64;
        // x tile fill: [128][64], 2048 float4 / 512 threads
        #pragma unroll
        for (int i = 0; i < 4; i++) {
            int idx = tid + i*512, r = idx >> 4, c4 = idx & 15;
            float4 v = *(const float4*)(x + (size_t)(row0+r)*CH + k0 + c4*4);
            xs[r*68 + hp(c4*4+0)] = f2tf(v.x);
            xs[r*68 + hp(c4*4+1)] = f2tf(v.y);
            xs[r*68 + hp(c4*4+2)] = f2tf(v.z);
            xs[r*68 + hp(c4*4+3)] = f2tf(v.w);
        }
        // W fill transposed: wt[n][hp(k)]
        #pragma unroll
        for (int ww = 0; ww < 3; ww++) {
            #pragma unroll
            for (int j = 0; j < 2; j++) {
                int hs0 = wg*8 + j*4;
                float4 v = *(const float4*)(Ws[ww] + (size_t)(k0+wr)*HS + hs0);
                int col = hp(wr);
                wt[(ww*64 + hs0+0)*68 + col] = f2tf(v.x);
                wt[(ww*64 + hs0+1)*68 + col] = f2tf(v.y);
                wt[(ww*64 + hs0+2)*68 + col] = f2tf(v.z);
                wt[(ww*64 + hs0+3)*68 + col] = f2tf(v.w);
            }
        }
        __syncthreads();

        const int arow = wrow + qr;
        #pragma unroll 1
        for (int ks = 0; ks < 8; ks++) {
            uint32_t a[4];
            uint2 t0 = *(uint2*)&xs[arow*68 + ks*8 + 2*m];
            uint2 t1 = *(uint2*)&xs[(arow+8)*68 + ks*8 + 2*m];
            a[0]=t0.x; a[2]=t0.y; a[1]=t1.x; a[3]=t1.y;
            #pragma unroll
            for (int nt = 0; nt < 12; nt++) {
                int ntg = wh*12 + nt;
                uint2 bb = *(uint2*)&wt[(ntg*8+qr)*68 + ks*8 + 2*m];
                uint32_t b[2] = {bb.x, bb.y};
                mma8(o[nt], a, b);
            }
        }
        __syncthreads();
    }
    float* dsts[3] = {g_q, g_k, g_v};
    const int rg = row0 + wrow + qr;
    #pragma unroll
    for (int nt = 0; nt < 12; nt++) {
        int ntg = wh*12 + nt;
        float* d = dsts[ntg >> 3];
        int col = (ntg & 7)*8 + 2*m;
        *(float2*)(d + (size_t)rg*HS + col)     = make_float2(o[nt][0], o[nt][1]);
        *(float2*)(d + (size_t)(rg+8)*HS + col) = make_float2(o[nt][2], o[nt][3]);
    }
}

// ----------------------------------------------------------- attention kernel
// grid 128 (4b x 32 qtiles of 128), block 512 = 2 groups x 256.
// Group g processes key tiles jt = g, g+2, ... (split-K: O,l purely additive
// because softmax uses no max subtraction). Q frags register-resident.
// S->P fragment conversion done with quad shuffles (no smem P buffer).
#define GRP_WORDS (128*68 + 64*132)
#define ATT_SMEM (2*GRP_WORDS*4)
__global__ __launch_bounds__(512, 1) void attn_tc(float* __restrict__ out)
{
    extern __shared__ __align__(16) uint32_t sm[];
    const int tid = threadIdx.x, w = tid >> 5, ln = tid & 31;
    const int m = ln & 3, qr = ln >> 2;
    const int g = w >> 3;              // key-parity group
    const int gtid = tid & 255;
    const int wrow = (w & 7) * 16;     // warp's 16 query rows
    uint32_t* Kg  = sm + g*GRP_WORDS;  // [128 key][68]  cols = hp(hs)
    uint32_t* VTg = Kg + 128*68;       // [64 hs ][132]  cols = hp(key)
    const int b = blockIdx.x >> 5, qt = blockIdx.x & 31;
    const float* qg = g_q + ((size_t)b*SEQ + qt*128) * HS;
    const float* kg = g_k + (size_t)b*SEQ*HS;
    const float* vg = g_v + (size_t)b*SEQ*HS;

    // stage Q into group-0 K area (all 512 threads), pull frags, then release
    #pragma unroll
    for (int i = 0; i < 4; i++) {
        int idx = tid + i*512, r = idx >> 4, c4 = idx & 15;
        float4 v = *(const float4*)(qg + (size_t)r*HS + c4*4);
        sm[r*68 + hp(c4*4+0)] = f2tf(v.x);
        sm[r*68 + hp(c4*4+1)] = f2tf(v.y);
        sm[r*68 + hp(c4*4+2)] = f2tf(v.z);
        sm[r*68 + hp(c4*4+3)] = f2tf(v.w);
    }
    __syncthreads();
    uint32_t q[8][4];
    {
        int r = wrow + qr;
        #pragma unroll
        for (int ks = 0; ks < 8; ks++) {
            uint2 t0 = *(uint2*)&sm[r*68 + ks*8 + 2*m];
            uint2 t1 = *(uint2*)&sm[(r+8)*68 + ks*8 + 2*m];
            q[ks][0]=t0.x; q[ks][2]=t0.y; q[ks][1]=t1.x; q[ks][3]=t1.y;
        }
    }
    __syncthreads();

    float o[8][4];
    #pragma unroll
    for (int nt = 0; nt < 8; nt++) { o[nt][0]=o[nt][1]=o[nt][2]=o[nt][3]=0.f; }
    float l0 = 0.f, l1 = 0.f;
    const int sl0 = (ln & ~3) | (m >> 1);
    const int sl1 = sl0 + 2;

    #pragma unroll 1
    for (int jt = g; jt <= qt; jt += 2) {
        const float* kt = kg + (size_t)jt*128*HS;
        const float* vt = vg + (size_t)jt*128*HS;
        // K fill: 2048 float4 / 256 threads
        #pragma unroll
        for (int i = 0; i < 8; i++) {
            int idx = gtid + i*256, r = idx >> 4, c4 = idx & 15;
            float4 v = *(const float4*)(kt + (size_t)r*HS + c4*4);
            Kg[r*68 + hp(c4*4+0)] = f2tf(v.x);
            Kg[r*68 + hp(c4*4+1)] = f2tf(v.y);
            Kg[r*68 + hp(c4*4+2)] = f2tf(v.z);
            Kg[r*68 + hp(c4*4+3)] = f2tf(v.w);
        }
        // VT fill transposed: VT[hs][hp(key)]
        {
            int kr = gtid & 127, half = gtid >> 7;
            int col = hp(kr);
            #pragma unroll
            for (int j = 0; j < 8; j++) {
                int hs0 = half*32 + j*4;
                float4 v = *(const float4*)(vt + (size_t)kr*HS + hs0);
                VTg[(hs0+0)*132 + col] = f2tf(v.x);
                VTg[(hs0+1)*132 + col] = f2tf(v.y);
                VTg[(hs0+2)*132 + col] = f2tf(v.z);
                VTg[(hs0+3)*132 + col] = f2tf(v.w);
            }
        }
        BARG(g+1);

        const bool diag = (jt == qt);
        const int rg0 = qt*128 + wrow + qr;
        const int rg1 = rg0 + 8;
        #pragma unroll 1
        for (int ch = 0; ch < 4; ch++) {
            float s[4][4];
            #pragma unroll
            for (int nt = 0; nt < 4; nt++)
                { s[nt][0]=s[nt][1]=s[nt][2]=s[nt][3]=0.f; }
            #pragma unroll 1
            for (int ks = 0; ks < 8; ks++) {
                #pragma unroll
                for (int nt = 0; nt < 4; nt++) {
                    uint2 bb = *(uint2*)&Kg[(ch*32+nt*8+qr)*68 + ks*8 + 2*m];
                    uint32_t bfr[2] = {bb.x, bb.y};
                    mma8(s[nt], q[ks], bfr);
                }
            }
            // softmax + in-register S->P fragment conversion + PV
            #pragma unroll
            for (int nt = 0; nt < 4; nt++) {
                const int kb = ch*32 + nt*8;
                const int kg0 = jt*128 + kb + 2*m;
                float p0 = ex2f(s[nt][0] * C_EXP);
                float p1 = ex2f(s[nt][1] * C_EXP);
                float p2 = ex2f(s[nt][2] * C_EXP);
                float p3 = ex2f(s[nt][3] * C_EXP);
                if (diag) {
                    if (kg0     > rg0) p0 = 0.f;
                    if (kg0 + 1 > rg0) p1 = 0.f;
                    if (kg0     > rg1) p2 = 0.f;
                    if (kg0 + 1 > rg1) p3 = 0.f;
                }
                uint32_t u0 = f2tf(p0), u1 = f2tf(p1), u2 = f2tf(p2), u3 = f2tf(p3);
                l0 += __uint_as_float(u0) + __uint_as_float(u1);
                l1 += __uint_as_float(u2) + __uint_as_float(u3);
                // quad shuffles: D cols {2m,2m+1} -> A cols {m, m+4}
                uint32_t e00 = __shfl_sync(0xffffffffu, u0, sl0);
                uint32_t e01 = __shfl_sync(0xffffffffu, u1, sl0);
                uint32_t e10 = __shfl_sync(0xffffffffu, u0, sl1);
                uint32_t e11 = __shfl_sync(0xffffffffu, u1, sl1);
                uint32_t e20 = __shfl_sync(0xffffffffu, u2, sl0);
                uint32_t e21 = __shfl_sync(0xffffffffu, u3, sl0);
                uint32_t e30 = __shfl_sync(0xffffffffu, u2, sl1);
                uint32_t e31 = __shfl_sync(0xffffffffu, u3, sl1);
                uint32_t a[4];
                a[0] = (m & 1) ? e01 : e00;
                a[2] = (m & 1) ? e11 : e10;
                a[1] = (m & 1) ? e21 : e20;
                a[3] = (m & 1) ? e31 : e30;
                // O += P_block @ V_block (one k-step of 8 keys)
                #pragma unroll
                for (int no = 0; no < 8; no++) {
                    uint2 bb = *(uint2*)&VTg[(no*8+qr)*132 + kb + 2*m];
                    uint32_t bfr[2] = {bb.x, bb.y};
                    mma8(o[no], a, bfr);
                }
            }
        }
        BARG(g+1);   // group done reading Kg/VTg before next fill
    }

    // ---- combine the two split-K partials ----
    __syncthreads();
    // quad-reduce l (lanes of a quad hold disjoint column subsets)
    l0 += __shfl_xor_sync(0xffffffffu, l0, 1);
    l0 += __shfl_xor_sync(0xffffffffu, l0, 2);
    l1 += __shfl_xor_sync(0xffffffffu, l1, 1);
    l1 += __shfl_xor_sync(0xffffffffu, l1, 2);

    float* Obuf = (float*)sm;            // [128][66]
    float* lbuf = (float*)sm + 128*66;   // [128]
    if (g == 0) {
        #pragma unroll
        for (int nt = 0; nt < 8; nt++) {
            *(float2*)&Obuf[(wrow+qr)*66 + nt*8 + 2*m]   = make_float2(o[nt][0], o[nt][1]);
            *(float2*)&Obuf[(wrow+qr+8)*66 + nt*8 + 2*m] = make_float2(o[nt][2], o[nt][3]);
        }
        if (m == 0) { lbuf[wrow+qr] = l0; lbuf[wrow+qr+8] = l1; }
    }
    __syncthreads();
    if (g == 1) {
        float inv0 = 1.f / (l0 + lbuf[wrow+qr]);
        float inv1 = 1.f / (l1 + lbuf[wrow+qr+8]);
        float* d = out + ((size_t)b*SEQ + qt*128 + wrow + qr) * HS;
        #pragma unroll
        for (int nt = 0; nt < 8; nt++) {
            float2 b0 = *(float2*)&Obuf[(wrow+qr)*66 + nt*8 + 2*m];
            float2 b1 = *(float2*)&Obuf[(wrow+qr+8)*66 + nt*8 + 2*m];
            *(float2*)(d + nt*8 + 2*m) =
                make_float2((o[nt][0]+b0.x)*inv0, (o[nt][1]+b0.y)*inv0);
            *(float2*)(d + (size_t)8*HS + nt*8 + 2*m) =
                make_float2((o[nt][2]+b1.x)*inv1, (o[nt][3]+b1.y)*inv1);
        }
    }
}

// ---------------------------------------------------------------------------
extern "C" void kernel_launch(void* const* d_in, const int* in_sizes, int n_in,
                              void* d_out, int out_size)
{
    const float* x  = (const float*)d_in[0];
    const float* Wq = (const float*)d_in[1];
    const float* Wk = (const float*)d_in[2];
    const float* Wv = (const float*)d_in[3];
    float* out = (float*)d_out;

    cudaFuncSetAttribute(qkv_tc,  cudaFuncAttributeMaxDynamicSharedMemorySize, QKV_SMEM);
    cudaFuncSetAttribute(attn_tc, cudaFuncAttributeMaxDynamicSharedMemorySize, ATT_SMEM);

    qkv_tc<<<128, 512, QKV_SMEM>>>(x, Wq, Wk, Wv);
    attn_tc<<<128, 512, ATT_SMEM>>>(out);
}

// round 6
// speedup vs baseline: 3.2396x; 1.5241x over previous
#include <cuda_runtime.h>
#include <cstdint>

#define BATCH 4
#define SEQ   4096
#define CH    1024
#define HS    64

__device__ float g_q[BATCH*SEQ*HS];
__device__ float g_k[BATCH*SEQ*HS];
__device__ float g_v[BATCH*SEQ*HS];

// ---------------------------------------------------------------- primitives
__device__ __forceinline__ uint32_t smem_u32(const void* p){
    uint32_t a;
    asm("{ .reg .u64 t; cvta.to.shared.u64 t, %1; cvt.u32.u64 %0, t; }":"=r"(a):"l"(p));
    return a;
}
__device__ __forceinline__ uint32_t f2tf(float f){
    uint32_t u; asm("cvt.rna.tf32.f32 %0, %1;" : "=r"(u) : "f"(f)); return u;
}
__device__ __forceinline__ float ex2f(float x){
    float y; asm("ex2.approx.ftz.f32 %0, %1;" : "=f"(y) : "f"(x)); return y;
}
__device__ __forceinline__ void mma8(float* d, const uint32_t* a, const uint32_t* b){
    asm volatile("mma.sync.aligned.m16n8k8.row.col.f32.tf32.tf32.f32 "
        "{%0,%1,%2,%3}, {%4,%5,%6,%7}, {%8,%9}, {%0,%1,%2,%3};"
        : "+f"(d[0]), "+f"(d[1]), "+f"(d[2]), "+f"(d[3])
        : "r"(a[0]), "r"(a[1]), "r"(a[2]), "r"(a[3]), "r"(b[0]), "r"(b[1]));
}
#define LDSM4(r0,r1,r2,r3,addr)                                              \
    asm volatile("ldmatrix.sync.aligned.m8n8.x4.shared.b16 {%0,%1,%2,%3}, [%4];" \
        : "=r"(r0), "=r"(r1), "=r"(r2), "=r"(r3) : "r"(addr))

#define BARG(id) asm volatile("bar.sync %0, 256;" :: "r"(id) : "memory")
#define C_EXP 0.18033688011112042f   // (1/8) * log2(e)

// ---------------------------------------------------------------- QKV kernel
// grid 128, block 512 (16 warps). 128 rows/CTA, warps split N=192 two ways.
// Natural layout + ldmatrix fragment loads.
#define QKV_SMEM ((128*68 + 192*68) * 4)
__global__ __launch_bounds__(512, 1) void qkv_tc(
    const float* __restrict__ x,  const float* __restrict__ Wq,
    const float* __restrict__ Wk, const float* __restrict__ Wv)
{
    extern __shared__ __align__(16) uint32_t sm[];
    uint32_t* xs = sm;             // [128 rows][68] natural (row stride 272B)
    uint32_t* wt = sm + 128*68;    // [192 n  ][68] natural
    const int tid = threadIdx.x, w = tid >> 5, ln = tid & 31;
    const int m = ln & 3, qr = ln >> 2;
    const int wh = w >> 3;          // n-half (0..1)
    const int wrow = (w & 7) * 16;  // warp's row base
    const int row0 = blockIdx.x * 128;
    const float* Ws[3] = {Wq, Wk, Wv};

    const int l7 = ln & 7, l3 = (ln >> 3) & 1, l4 = (ln >> 4) & 1;
    const uint32_t offA  = (uint32_t)((l7 + l3*8)*272 + l4*16);   // A frag x4
    const uint32_t offWB = (uint32_t)((l7 + l4*8)*272 + l3*16);   // B pair x4
    const uint32_t XB = smem_u32(xs), WB = smem_u32(wt);

    float o[12][4];
    #pragma unroll
    for (int i = 0; i < 12; i++) { o[i][0]=o[i][1]=o[i][2]=o[i][3]=0.f; }

    const int wr = tid & 63;        // W fill: k-row
    const int wg = tid >> 6;        // hs octant (0..7)

    #pragma unroll 1
    for (int c = 0; c < 16; c++) {
        const int k0 = c * 64;
        // x tile fill: [128][64] natural, STS.128
        #pragma unroll
        for (int i = 0; i < 4; i++) {
            int idx = tid + i*512, r = idx >> 4, c4 = idx & 15;
            float4 v = *(const float4*)(x + (size_t)(row0+r)*CH + k0 + c4*4);
            uint4 u = make_uint4(f2tf(v.x), f2tf(v.y), f2tf(v.z), f2tf(v.w));
            *(uint4*)((char*)xs + r*272 + c4*16) = u;
        }
        // W fill transposed: wt[n][k] natural
        #pragma unroll
        for (int ww = 0; ww < 3; ww++) {
            #pragma unroll
            for (int j = 0; j < 2; j++) {
                int hs0 = wg*8 + j*4;
                float4 v = *(const float4*)(Ws[ww] + (size_t)(k0+wr)*HS + hs0);
                wt[(ww*64 + hs0+0)*68 + wr] = f2tf(v.x);
                wt[(ww*64 + hs0+1)*68 + wr] = f2tf(v.y);
                wt[(ww*64 + hs0+2)*68 + wr] = f2tf(v.z);
                wt[(ww*64 + hs0+3)*68 + wr] = f2tf(v.w);
            }
        }
        __syncthreads();

        #pragma unroll 1
        for (int ks = 0; ks < 8; ks++) {
            uint32_t a[4];
            LDSM4(a[0], a[1], a[2], a[3], XB + (uint32_t)(wrow*272 + ks*32) + offA);
            #pragma unroll
            for (int np = 0; np < 6; np++) {
                uint32_t bf[4];
                LDSM4(bf[0], bf[1], bf[2], bf[3],
                      WB + (uint32_t)(((wh*12 + 2*np)*8)*272 + ks*32) + offWB);
                mma8(o[2*np],   a, bf);
                mma8(o[2*np+1], a, bf+2);
            }
        }
        __syncthreads();
    }
    float* dsts[3] = {g_q, g_k, g_v};
    const int rg = row0 + wrow + qr;
    #pragma unroll
    for (int nt = 0; nt < 12; nt++) {
        int ntg = wh*12 + nt;
        float* d = dsts[ntg >> 3];
        int col = (ntg & 7)*8 + 2*m;
        *(float2*)(d + (size_t)rg*HS + col)     = make_float2(o[nt][0], o[nt][1]);
        *(float2*)(d + (size_t)(rg+8)*HS + col) = make_float2(o[nt][2], o[nt][3]);
    }
}

// ----------------------------------------------------------- attention kernel
// grid 128 (4b x 32 qtiles of 128), block 512 = 2 groups x 256.
// Group g: key tiles jt = g, g+2, ... (split-K; softmax has no max subtraction
// so O,l are purely additive). Q frags register-resident via ldmatrix.
// Natural smem layouts; all fragment loads via ldmatrix.x4.
#define GRP_WORDS (128*68 + 64*132)
#define ATT_SMEM (2*GRP_WORDS*4)
__global__ __launch_bounds__(512, 1) void attn_tc(float* __restrict__ out)
{
    extern __shared__ __align__(16) uint32_t sm[];
    const int tid = threadIdx.x, w = tid >> 5, ln = tid & 31;
    const int m = ln & 3, qr = ln >> 2;
    const int g = w >> 3;              // key-parity group
    const int gtid = tid & 255;
    const int wrow = (w & 7) * 16;     // warp's 16 query rows
    uint32_t* Kg  = sm + g*GRP_WORDS;  // [128 key][68] natural (272B rows)
    uint32_t* VTg = Kg + 128*68;       // [64 hs ][132] natural (528B rows)
    const int b = blockIdx.x >> 5, qt = blockIdx.x & 31;
    const float* qg = g_q + ((size_t)b*SEQ + qt*128) * HS;
    const float* kg = g_k + (size_t)b*SEQ*HS;
    const float* vg = g_v + (size_t)b*SEQ*HS;

    const int l7 = ln & 7, l3 = (ln >> 3) & 1, l4 = (ln >> 4) & 1;
    const uint32_t offKB = (uint32_t)(l7*272 + (ln >> 3)*16);       // B pairs (ks,ks+1)
    const uint32_t offA  = (uint32_t)((l7 + l3*8)*272 + l4*16);     // A frag
    const uint32_t offVT = (uint32_t)((l7 + l4*8)*528 + l3*16);     // VT B pairs (n,n+1)
    const uint32_t KB = smem_u32(Kg), VB = smem_u32(VTg);
    const uint32_t SB = smem_u32(sm);

    // stage Q natural into group-0 area (all 512 threads), pull frags, release
    #pragma unroll
    for (int i = 0; i < 4; i++) {
        int idx = tid + i*512, r = idx >> 4, c4 = idx & 15;
        float4 v = *(const float4*)(qg + (size_t)r*HS + c4*4);
        uint4 u = make_uint4(f2tf(v.x), f2tf(v.y), f2tf(v.z), f2tf(v.w));
        *(uint4*)((char*)sm + r*272 + c4*16) = u;
    }
    __syncthreads();
    uint32_t q[8][4];
    {
        uint32_t qb = SB + (uint32_t)(wrow*272) + offA;
        #pragma unroll
        for (int ks = 0; ks < 8; ks++)
            LDSM4(q[ks][0], q[ks][1], q[ks][2], q[ks][3], qb + ks*32);
    }
    __syncthreads();

    float o[8][4];
    #pragma unroll
    for (int nt = 0; nt < 8; nt++) { o[nt][0]=o[nt][1]=o[nt][2]=o[nt][3]=0.f; }
    float l0 = 0.f, l1 = 0.f;
    const int sl0 = (ln & ~3) | (m >> 1);
    const int sl1 = sl0 + 2;

    #pragma unroll 1
    for (int jt = g; jt <= qt; jt += 2) {
        const float* kt = kg + (size_t)jt*128*HS;
        const float* vt = vg + (size_t)jt*128*HS;
        // K fill: natural, STS.128
        #pragma unroll
        for (int i = 0; i < 8; i++) {
            int idx = gtid + i*256, r = idx >> 4, c4 = idx & 15;
            float4 v = *(const float4*)(kt + (size_t)r*HS + c4*4);
            uint4 u = make_uint4(f2tf(v.x), f2tf(v.y), f2tf(v.z), f2tf(v.w));
            *(uint4*)((char*)Kg + r*272 + c4*16) = u;
        }
        // VT fill transposed: VT[hs][key] natural
        {
            int kr = gtid & 127, half = gtid >> 7;
            #pragma unroll
            for (int j = 0; j < 8; j++) {
                int hs0 = half*32 + j*4;
                float4 v = *(const float4*)(vt + (size_t)kr*HS + hs0);
                VTg[(hs0+0)*132 + kr] = f2tf(v.x);
                VTg[(hs0+1)*132 + kr] = f2tf(v.y);
                VTg[(hs0+2)*132 + kr] = f2tf(v.z);
                VTg[(hs0+3)*132 + kr] = f2tf(v.w);
            }
        }
        BARG(g+1);

        const bool diag = (jt == qt);
        const int rg0 = qt*128 + wrow + qr;
        const int rg1 = rg0 + 8;
        #pragma unroll 1
        for (int ch = 0; ch < 4; ch++) {
            float s[4][4];
            #pragma unroll
            for (int nt = 0; nt < 4; nt++)
                { s[nt][0]=s[nt][1]=s[nt][2]=s[nt][3]=0.f; }
            // S = Q K^T, ks processed in pairs via LDSM.x4
            #pragma unroll
            for (int ksp = 0; ksp < 4; ksp++) {
                #pragma unroll
                for (int nt = 0; nt < 4; nt++) {
                    uint32_t bf[4];
                    LDSM4(bf[0], bf[1], bf[2], bf[3],
                          KB + (uint32_t)((ch*32 + nt*8)*272 + ksp*64) + offKB);
                    mma8(s[nt], q[2*ksp],   bf);
                    mma8(s[nt], q[2*ksp+1], bf+2);
                }
            }
            // softmax + in-register S->P conversion + PV
            #pragma unroll
            for (int nt = 0; nt < 4; nt++) {
                const int kb = ch*32 + nt*8;
                const int kg0 = jt*128 + kb + 2*m;
                float p0 = ex2f(s[nt][0] * C_EXP);
                float p1 = ex2f(s[nt][1] * C_EXP);
                float p2 = ex2f(s[nt][2] * C_EXP);
                float p3 = ex2f(s[nt][3] * C_EXP);
                if (diag) {
                    if (kg0     > rg0) p0 = 0.f;
                    if (kg0 + 1 > rg0) p1 = 0.f;
                    if (kg0     > rg1) p2 = 0.f;
                    if (kg0 + 1 > rg1) p3 = 0.f;
                }
                uint32_t u0 = f2tf(p0), u1 = f2tf(p1), u2 = f2tf(p2), u3 = f2tf(p3);
                l0 += __uint_as_float(u0) + __uint_as_float(u1);
                l1 += __uint_as_float(u2) + __uint_as_float(u3);
                // quad shuffles: D cols {2m,2m+1} -> A cols {m, m+4}
                uint32_t e00 = __shfl_sync(0xffffffffu, u0, sl0);
                uint32_t e01 = __shfl_sync(0xffffffffu, u1, sl0);
                uint32_t e10 = __shfl_sync(0xffffffffu, u0, sl1);
                uint32_t e11 = __shfl_sync(0xffffffffu, u1, sl1);
                uint32_t e20 = __shfl_sync(0xffffffffu, u2, sl0);
                uint32_t e21 = __shfl_sync(0xffffffffu, u3, sl0);
                uint32_t e30 = __shfl_sync(0xffffffffu, u2, sl1);
                uint32_t e31 = __shfl_sync(0xffffffffu, u3, sl1);
                uint32_t a[4];
                a[0] = (m & 1) ? e01 : e00;
                a[2] = (m & 1) ? e11 : e10;
                a[1] = (m & 1) ? e21 : e20;
                a[3] = (m & 1) ? e31 : e30;
                // O += P_block @ V_block; VT frags in (n, n+1) pairs
                #pragma unroll
                for (int np = 0; np < 4; np++) {
                    uint32_t vb[4];
                    LDSM4(vb[0], vb[1], vb[2], vb[3],
                          VB + (uint32_t)((2*np*8)*528 + kb*4) + offVT);
                    mma8(o[2*np],   a, vb);
                    mma8(o[2*np+1], a, vb+2);
                }
            }
        }
        BARG(g+1);   // group done reading Kg/VTg before next fill
    }

    // ---- combine the two split-K partials ----
    __syncthreads();
    l0 += __shfl_xor_sync(0xffffffffu, l0, 1);
    l0 += __shfl_xor_sync(0xffffffffu, l0, 2);
    l1 += __shfl_xor_sync(0xffffffffu, l1, 1);
    l1 += __shfl_xor_sync(0xffffffffu, l1, 2);

    float* Obuf = (float*)sm;            // [128][66]
    float* lbuf = (float*)sm + 128*66;   // [128]
    if (g == 0) {
        #pragma unroll
        for (int nt = 0; nt < 8; nt++) {
            *(float2*)&Obuf[(wrow+qr)*66 + nt*8 + 2*m]   = make_float2(o[nt][0], o[nt][1]);
            *(float2*)&Obuf[(wrow+qr+8)*66 + nt*8 + 2*m] = make_float2(o[nt][2], o[nt][3]);
        }
        if (m == 0) { lbuf[wrow+qr] = l0; lbuf[wrow+qr+8] = l1; }
    }
    __syncthreads();
    if (g == 1) {
        float inv0 = 1.f / (l0 + lbuf[wrow+qr]);
        float inv1 = 1.f / (l1 + lbuf[wrow+qr+8]);
        float* d = out + ((size_t)b*SEQ + qt*128 + wrow + qr) * HS;
        #pragma unroll
        for (int nt = 0; nt < 8; nt++) {
            float2 b0 = *(float2*)&Obuf[(wrow+qr)*66 + nt*8 + 2*m];
            float2 b1 = *(float2*)&Obuf[(wrow+qr+8)*66 + nt*8 + 2*m];
            *(float2*)(d + nt*8 + 2*m) =
                make_float2((o[nt][0]+b0.x)*inv0, (o[nt][1]+b0.y)*inv0);
            *(float2*)(d + (size_t)8*HS + nt*8 + 2*m) =
                make_float2((o[nt][2]+b1.x)*inv1, (o[nt][3]+b1.y)*inv1);
        }
    }
}

// ---------------------------------------------------------------------------
extern "C" void kernel_launch(void* const* d_in, const int* in_sizes, int n_in,
                              void* d_out, int out_size)
{
    const float* x  = (const float*)d_in[0];
    const float* Wq = (const float*)d_in[1];
    const float* Wk = (const float*)d_in[2];
    const float* Wv = (const float*)d_in[3];
    float* out = (float*)d_out;

    cudaFuncSetAttribute(qkv_tc,  cudaFuncAttributeMaxDynamicSharedMemorySize, QKV_SMEM);
    cudaFuncSetAttribute(attn_tc, cudaFuncAttributeMaxDynamicSharedMemorySize, ATT_SMEM);

    qkv_tc<<<128, 512, QKV_SMEM>>>(x, Wq, Wk, Wv);
    attn_tc<<<128, 512, ATT_SMEM>>>(out);
}